// round 8
// baseline (speedup 1.0000x reference)
#include <cuda_runtime.h>
#include <cstdint>
#include <cstddef>

#define BATCH 64
#define SEQT  512
#define DIN   256
#define HDIM  1024
#define DOUT  128
#define GRID  128

typedef unsigned long long u64;

// ---------------- scratch (device globals: allocation-free) ----------------
__device__ __align__(16) static float g_P[(size_t)BATCH * SEQT * HDIM]; // pre-activations
__device__ __align__(16) static float g_S[(size_t)BATCH * SEQT * HDIM]; // layer outputs / h
__device__ volatile unsigned g_flags[GRID];                             // barrier flags (zero-init)

// ---------------- packed f32x2 helpers ----------------
__device__ __forceinline__ void fma2(u64 &d, u64 a, u64 b) {
    asm("fma.rn.f32x2 %0, %1, %2, %0;" : "+l"(d) : "l"(a), "l"(b));
}
__device__ __forceinline__ u64 add2(u64 a, u64 b) {
    u64 r; asm("add.rn.f32x2 %0, %1, %2;" : "=l"(r) : "l"(a), "l"(b)); return r;
}
__device__ __forceinline__ float2 up2(u64 v) {
    float2 f; asm("mov.b64 {%0, %1}, %2;" : "=f"(f.x), "=f"(f.y) : "l"(v)); return f;
}

__device__ __forceinline__ uint32_t smem_u32(const void* p) {
    uint32_t a;
    asm("{ .reg .u64 t; cvta.to.shared.u64 t, %1; cvt.u32.u64 %0, t; }" : "=r"(a) : "l"(p));
    return a;
}
__device__ __forceinline__ void cpasync16(uint32_t dst, const void* src) {
    asm volatile("cp.async.cg.shared.global [%0], [%1], 16;" :: "r"(dst), "l"(src));
}
__device__ __forceinline__ void cpasync_commit_wait() {
    asm volatile("cp.async.commit_group;");
    asm volatile("cp.async.wait_group 0;" ::: "memory");
}

// ---------------- group barrier: 4 independent groups of 32 CTAs ----------------
__device__ __forceinline__ void gsync(unsigned gen, int gbase) {
    __syncthreads();
    if (threadIdx.x == 0) {
        __threadfence();                 // release prior global writes
        g_flags[blockIdx.x] = gen;       // volatile store
    }
    if (threadIdx.x < 32) {
        while (g_flags[gbase + threadIdx.x] < gen) { }
    }
    __syncthreads();
}

// ============================================================================
// Projection GEMM: C[32768][1024] = A[32768][K] @ W[1024][K]^T + (bi + bh)
// ============================================================================
__global__ void __launch_bounds__(256, 2) proj_kernel(
    const float* __restrict__ A, const float* __restrict__ W,
    const float* __restrict__ bi, const float* __restrict__ bh,
    float* __restrict__ C, int K)
{
    __shared__ __align__(16) float sA[16 * 132];
    __shared__ __align__(16) float sB[16 * 132];

    const int tid = threadIdx.x;
    const int tm = blockIdx.x >> 3;
    const int tn = blockIdx.x & 7;
    const int ty = tid >> 4;
    const int tx = tid & 15;
    const int lr = tid >> 2;
    const int lq = tid & 3;

    u64 acc[8][4];
    #pragma unroll
    for (int i = 0; i < 8; i++)
        #pragma unroll
        for (int j = 0; j < 4; j++) acc[i][j] = 0ull;

    const float* Ab = A + (size_t)(tm * 128) * K;
    const float* Wb = W + (size_t)(tn * 128) * K;

    for (int kc = 0; kc < K; kc += 16) {
        __syncthreads();
        #pragma unroll
        for (int p = 0; p < 2; p++) {
            const int rr = lr + p * 64;
            const float4 a4 = __ldg((const float4*)(Ab + (size_t)rr * K + kc + lq * 4));
            const float4 w4 = __ldg((const float4*)(Wb + (size_t)rr * K + kc + lq * 4));
            sA[(lq * 4 + 0) * 132 + rr] = a4.x;
            sA[(lq * 4 + 1) * 132 + rr] = a4.y;
            sA[(lq * 4 + 2) * 132 + rr] = a4.z;
            sA[(lq * 4 + 3) * 132 + rr] = a4.w;
            sB[(lq * 4 + 0) * 132 + rr] = w4.x;
            sB[(lq * 4 + 1) * 132 + rr] = w4.y;
            sB[(lq * 4 + 2) * 132 + rr] = w4.z;
            sB[(lq * 4 + 3) * 132 + rr] = w4.w;
        }
        __syncthreads();
        #pragma unroll
        for (int kk = 0; kk < 16; kk++) {
            const float4 a0 = *(const float4*)&sA[kk * 132 + ty * 4];
            const float4 a1 = *(const float4*)&sA[kk * 132 + 64 + ty * 4];
            const ulonglong2 bq0 = *(const ulonglong2*)&sB[kk * 132 + tx * 4];
            const ulonglong2 bq1 = *(const ulonglong2*)&sB[kk * 132 + 64 + tx * 4];
            const float am[8] = {a0.x, a0.y, a0.z, a0.w, a1.x, a1.y, a1.z, a1.w};
            #pragma unroll
            for (int i = 0; i < 8; i++) {
                u64 ad;
                asm("mov.b64 %0, {%1, %1};" : "=l"(ad) : "f"(am[i]));
                fma2(acc[i][0], ad, bq0.x);
                fma2(acc[i][1], ad, bq0.y);
                fma2(acc[i][2], ad, bq1.x);
                fma2(acc[i][3], ad, bq1.y);
            }
        }
    }

    const int n0 = tn * 128 + tx * 4;
    const int n1 = n0 + 64;
    float4 bia0, bia1;
    {
        const float4 i0 = __ldg((const float4*)(bi + n0));
        const float4 h0 = __ldg((const float4*)(bh + n0));
        const float4 i1 = __ldg((const float4*)(bi + n1));
        const float4 h1 = __ldg((const float4*)(bh + n1));
        bia0 = make_float4(i0.x + h0.x, i0.y + h0.y, i0.z + h0.z, i0.w + h0.w);
        bia1 = make_float4(i1.x + h1.x, i1.y + h1.y, i1.z + h1.z, i1.w + h1.w);
    }
    #pragma unroll
    for (int i = 0; i < 8; i++) {
        const int m = tm * 128 + (i < 4 ? ty * 4 + i : 64 + ty * 4 + (i - 4));
        const float2 c0 = up2(acc[i][0]), c1 = up2(acc[i][1]);
        const float2 c2 = up2(acc[i][2]), c3 = up2(acc[i][3]);
        *(float4*)(C + (size_t)m * HDIM + n0) =
            make_float4(c0.x + bia0.x, c0.y + bia0.y, c1.x + bia0.z, c1.y + bia0.w);
        *(float4*)(C + (size_t)m * HDIM + n1) =
            make_float4(c2.x + bia1.x, c2.y + bia1.y, c3.x + bia1.z, c3.y + bia1.w);
    }
}

// ============================================================================
// Recurrent scan, register-resident weights, 512 threads / 16 warps.
// 128 CTAs, 1 CTA/SM, CTA tile [16b x 32o].
// Warp w owns k-slice [64w, 64w+64); lane l owns output o0+l.
// wreg = 32 u64 (64 fp32 weights) per lane, resident whole layer.
// h broadcast from smem (all lanes of a warp read same address).
// Batches in 2 passes of 8 (keeps regs < 128 @ 512 thr).
// Reduce: 16 warp-partials u64[16][512] in smem, 1 output/thread final pass.
// ============================================================================
#define SM_H   0                          // hS[16][1024] floats
#define SM_R   (16 * 1024)                // red: u64[16][512]
#define SCAN_SMEM_BYTES ((16 * 1024) * 4 + 16 * 512 * 8)   // 131,072 B

__global__ void __launch_bounds__(512, 1) scan_kernel(
    const float* __restrict__ P, float* __restrict__ S,
    const float* __restrict__ Whh)
{
    extern __shared__ __align__(16) float sm[];
    float* hS = sm + SM_H;
    u64*   red = (u64*)(sm + SM_R);

    const int tid  = threadIdx.x;
    const int cta  = blockIdx.x;
    const int gbase = cta & ~31;        // barrier group base
    const int b0 = (cta >> 5) * 16;     // batch block
    const int o0 = (cta & 31) * 32;     // output block
    const int warp = tid >> 5;          // k-slice owner: [warp*64, +64)
    const int lane = tid & 31;          // output owner: o0 + lane
    const int kb = warp * 64;

    // ---- load this lane's weight slice into registers (once per layer) ----
    u64 wreg[32];
    {
        const float* wrow = Whh + (size_t)(o0 + lane) * HDIM + kb;
        #pragma unroll
        for (int c = 0; c < 16; c++) {
            const float4 w4 = __ldg((const float4*)(wrow + c * 4));
            wreg[2 * c]     = ((const u64*)&w4)[0];
            wreg[2 * c + 1] = ((const u64*)&w4)[1];
        }
    }

    unsigned gen = g_flags[cta];        // persists across launches

    // Epilogue mapping: one (batch, output) per thread
    const int eb = tid >> 5;            // 0..15 batch (== warp)
    const int eo = tid & 31;            // 0..31 output (== lane)
    const size_t erow = ((size_t)(b0 + eb) * SEQT) * HDIM + o0 + eo;

    // t = 0
    S[erow] = fmaxf(P[erow], 0.f);
    gen++; gsync(gen, gbase);

    const uint32_t hS_a = smem_u32(hS);
    const float* Sb = S + (size_t)b0 * SEQT * HDIM;

    for (int t = 1; t < SEQT; t++) {
        const float pv = __ldg(P + erow + (size_t)t * HDIM);

        // CTA-wide staging of h_{t-1}[b0..b0+16) (cp.async .cg = L2-coherent)
        // 16 rows x 256 float4 = 4096 float4 = 8 passes x 512 threads
        {
            const size_t tprev = (size_t)(t - 1) * HDIM;
            #pragma unroll
            for (int p = 0; p < 8; p++) {
                const int i = p * 512 + tid;
                const int bb = i >> 8, qq = i & 255;     // 256 float4 per row
                cpasync16(hS_a + (uint32_t)(bb * 1024 + qq * 4) * 4,
                          Sb + (size_t)bb * SEQT * HDIM + tprev + qq * 4);
            }
            cpasync_commit_wait();
        }
        __syncthreads();

        // ---- compute: 2 passes x 8 batches x 1 output x 64 k ----
        #pragma unroll
        for (int bp = 0; bp < 2; bp++) {
            u64 acc[8];
            #pragma unroll
            for (int b = 0; b < 8; b++) {
                const ulonglong2* hrow =
                    (const ulonglong2*)&hS[(bp * 8 + b) * 1024 + kb];
                u64 a0 = 0ull, a1 = 0ull;
                #pragma unroll
                for (int c = 0; c < 16; c++) {
                    const ulonglong2 hp = hrow[c];   // warp-broadcast
                    fma2(a0, hp.x, wreg[2 * c]);
                    fma2(a1, hp.y, wreg[2 * c + 1]);
                }
                acc[b] = add2(a0, a1);
            }
            #pragma unroll
            for (int b = 0; b < 8; b++)
                red[warp * 512 + (bp * 8 + b) * 32 + lane] = acc[b];
        }
        __syncthreads();

        // final reduce over 16 warps for this thread's (eb, eo)
        {
            u64 s = red[tid];
            #pragma unroll
            for (int w16 = 1; w16 < 16; w16++)
                s = add2(s, red[w16 * 512 + tid]);
            const float2 f = up2(s);
            S[erow + (size_t)t * HDIM] = fmaxf(f.x + f.y + pv, 0.f);
        }
        gen++; gsync(gen, gbase);
    }
}

// ============================================================================
// FC: out[64][128] = S[:, T-1, :] @ fc_w^T + fc_b
// ============================================================================
__global__ void __launch_bounds__(128) fc_kernel(
    const float* __restrict__ S, const float* __restrict__ fw,
    const float* __restrict__ fb, float* __restrict__ out)
{
    __shared__ __align__(16) float sx[HDIM];
    const int b = blockIdx.x, tid = threadIdx.x;
    const float* xrow = S + ((size_t)b * SEQT + (SEQT - 1)) * HDIM;
    for (int i = tid; i < HDIM / 4; i += 128)
        *(float4*)&sx[i * 4] = __ldcg((const float4*)(xrow + i * 4));
    __syncthreads();
    float acc = 0.f;
    const float* wrow = fw + (size_t)tid * HDIM;
    #pragma unroll 8
    for (int q = 0; q < HDIM / 4; q++) {
        const float4 w4 = __ldg((const float4*)(wrow + q * 4));
        const float4 x4 = *(const float4*)&sx[q * 4];
        acc += w4.x * x4.x + w4.y * x4.y + w4.z * x4.z + w4.w * x4.w;
    }
    out[(size_t)b * DOUT + tid] = acc + __ldg(fb + tid);
}

// ============================================================================
extern "C" void kernel_launch(void* const* d_in, const int* in_sizes, int n_in,
                              void* d_out, int out_size)
{
    const float* x    = (const float*)d_in[0];   // [64,512,256]
    const float* wih0 = (const float*)d_in[1];   // [1024,256]
    const float* wihr = (const float*)d_in[2];   // [2,1024,1024]
    const float* whh  = (const float*)d_in[3];   // [3,1024,1024]
    const float* bih  = (const float*)d_in[4];   // [3,1024]
    const float* bhh  = (const float*)d_in[5];   // [3,1024]
    const float* fcw  = (const float*)d_in[6];   // [128,1024]
    const float* fcb  = (const float*)d_in[7];   // [128]
    float* out = (float*)d_out;                  // [64,128]

    cudaFuncSetAttribute(scan_kernel, cudaFuncAttributeMaxDynamicSharedMemorySize,
                         SCAN_SMEM_BYTES);

    void *pP = nullptr, *pS = nullptr;
    cudaGetSymbolAddress(&pP, g_P);
    cudaGetSymbolAddress(&pS, g_S);
    float* P  = (float*)pP;
    float* Sq = (float*)pS;

    proj_kernel<<<2048, 256>>>(x, wih0, bih, bhh, P, DIN);
    scan_kernel<<<GRID, 512, SCAN_SMEM_BYTES>>>(P, Sq, whh);
    proj_kernel<<<2048, 256>>>(Sq, wihr, bih + HDIM, bhh + HDIM, P, HDIM);
    scan_kernel<<<GRID, 512, SCAN_SMEM_BYTES>>>(P, Sq, whh + (size_t)HDIM * HDIM);
    proj_kernel<<<2048, 256>>>(Sq, wihr + (size_t)HDIM * HDIM, bih + 2 * HDIM, bhh + 2 * HDIM, P, HDIM);
    scan_kernel<<<GRID, 512, SCAN_SMEM_BYTES>>>(P, Sq, whh + 2 * (size_t)HDIM * HDIM);
    fc_kernel<<<BATCH, 128>>>(Sq, fcw, fcb, out);
}

// round 9
// speedup vs baseline: 1.0329x; 1.0329x over previous
#include <cuda_runtime.h>
#include <cstdint>
#include <cstddef>

#define BATCH 64
#define SEQT  512
#define DIN   256
#define HDIM  1024
#define DOUT  128
#define GRID  128

typedef unsigned long long u64;

// ---------------- scratch (device globals: allocation-free) ----------------
__device__ __align__(16) static float g_P[(size_t)BATCH * SEQT * HDIM]; // pre-activations
__device__ __align__(16) static float g_S[(size_t)BATCH * SEQT * HDIM]; // layer outputs / h
__device__ volatile unsigned g_flags[GRID];                             // barrier flags (zero-init)

// ---------------- packed f32x2 helpers ----------------
__device__ __forceinline__ void fma2(u64 &d, u64 a, u64 b) {
    asm("fma.rn.f32x2 %0, %1, %2, %0;" : "+l"(d) : "l"(a), "l"(b));
}
__device__ __forceinline__ u64 add2(u64 a, u64 b) {
    u64 r; asm("add.rn.f32x2 %0, %1, %2;" : "=l"(r) : "l"(a), "l"(b)); return r;
}
__device__ __forceinline__ float2 up2(u64 v) {
    float2 f; asm("mov.b64 {%0, %1}, %2;" : "=f"(f.x), "=f"(f.y) : "l"(v)); return f;
}

__device__ __forceinline__ uint32_t smem_u32(const void* p) {
    uint32_t a;
    asm("{ .reg .u64 t; cvta.to.shared.u64 t, %1; cvt.u32.u64 %0, t; }" : "=r"(a) : "l"(p));
    return a;
}

// ---------------- mbarrier + TMA bulk helpers ----------------
__device__ __forceinline__ void mbar_init(uint32_t a, uint32_t cnt) {
    asm volatile("mbarrier.init.shared.b64 [%0], %1;" :: "r"(a), "r"(cnt) : "memory");
}
__device__ __forceinline__ void fence_proxy_async_shared() {
    asm volatile("fence.proxy.async.shared::cta;" ::: "memory");
}
__device__ __forceinline__ void mbar_expect_tx(uint32_t a, uint32_t bytes) {
    asm volatile("mbarrier.arrive.expect_tx.shared.b64 _, [%0], %1;"
                 :: "r"(a), "r"(bytes) : "memory");
}
__device__ __forceinline__ void bulk_g2s(uint32_t dst, const void* src,
                                         uint32_t bytes, uint32_t mbar) {
    asm volatile(
        "cp.async.bulk.shared::cta.global.mbarrier::complete_tx::bytes [%0], [%1], %2, [%3];"
        :: "r"(dst), "l"(src), "r"(bytes), "r"(mbar) : "memory");
}
__device__ __forceinline__ void mbar_wait(uint32_t a, uint32_t ph) {
    asm volatile(
        "{\n\t"
        ".reg .pred P;\n\t"
        "W_%=:\n\t"
        "mbarrier.try_wait.parity.acquire.cta.shared::cta.b64 P, [%0], %1;\n\t"
        "@P bra D_%=;\n\t"
        "bra W_%=;\n\t"
        "D_%=:\n\t"
        "}"
        :: "r"(a), "r"(ph) : "memory");
}

// ---------------- group barrier: 4 independent groups of 32 CTAs ----------------
__device__ __forceinline__ void gsync(unsigned gen, int gbase) {
    __syncthreads();
    if (threadIdx.x == 0) {
        __threadfence();                 // release prior global writes
        g_flags[blockIdx.x] = gen;       // volatile store
    }
    if (threadIdx.x < 32) {
        while (g_flags[gbase + threadIdx.x] < gen) { }
    }
    __syncthreads();
}

// ============================================================================
// Projection GEMM: C[32768][1024] = A[32768][K] @ W[1024][K]^T + (bi + bh)
// ============================================================================
__global__ void __launch_bounds__(256, 2) proj_kernel(
    const float* __restrict__ A, const float* __restrict__ W,
    const float* __restrict__ bi, const float* __restrict__ bh,
    float* __restrict__ C, int K)
{
    __shared__ __align__(16) float sA[16 * 132];
    __shared__ __align__(16) float sB[16 * 132];

    const int tid = threadIdx.x;
    const int tm = blockIdx.x >> 3;
    const int tn = blockIdx.x & 7;
    const int ty = tid >> 4;
    const int tx = tid & 15;
    const int lr = tid >> 2;
    const int lq = tid & 3;

    u64 acc[8][4];
    #pragma unroll
    for (int i = 0; i < 8; i++)
        #pragma unroll
        for (int j = 0; j < 4; j++) acc[i][j] = 0ull;

    const float* Ab = A + (size_t)(tm * 128) * K;
    const float* Wb = W + (size_t)(tn * 128) * K;

    for (int kc = 0; kc < K; kc += 16) {
        __syncthreads();
        #pragma unroll
        for (int p = 0; p < 2; p++) {
            const int rr = lr + p * 64;
            const float4 a4 = __ldg((const float4*)(Ab + (size_t)rr * K + kc + lq * 4));
            const float4 w4 = __ldg((const float4*)(Wb + (size_t)rr * K + kc + lq * 4));
            sA[(lq * 4 + 0) * 132 + rr] = a4.x;
            sA[(lq * 4 + 1) * 132 + rr] = a4.y;
            sA[(lq * 4 + 2) * 132 + rr] = a4.z;
            sA[(lq * 4 + 3) * 132 + rr] = a4.w;
            sB[(lq * 4 + 0) * 132 + rr] = w4.x;
            sB[(lq * 4 + 1) * 132 + rr] = w4.y;
            sB[(lq * 4 + 2) * 132 + rr] = w4.z;
            sB[(lq * 4 + 3) * 132 + rr] = w4.w;
        }
        __syncthreads();
        #pragma unroll
        for (int kk = 0; kk < 16; kk++) {
            const float4 a0 = *(const float4*)&sA[kk * 132 + ty * 4];
            const float4 a1 = *(const float4*)&sA[kk * 132 + 64 + ty * 4];
            const ulonglong2 bq0 = *(const ulonglong2*)&sB[kk * 132 + tx * 4];
            const ulonglong2 bq1 = *(const ulonglong2*)&sB[kk * 132 + 64 + tx * 4];
            const float am[8] = {a0.x, a0.y, a0.z, a0.w, a1.x, a1.y, a1.z, a1.w};
            #pragma unroll
            for (int i = 0; i < 8; i++) {
                u64 ad;
                asm("mov.b64 %0, {%1, %1};" : "=l"(ad) : "f"(am[i]));
                fma2(acc[i][0], ad, bq0.x);
                fma2(acc[i][1], ad, bq0.y);
                fma2(acc[i][2], ad, bq1.x);
                fma2(acc[i][3], ad, bq1.y);
            }
        }
    }

    const int n0 = tn * 128 + tx * 4;
    const int n1 = n0 + 64;
    float4 bia0, bia1;
    {
        const float4 i0 = __ldg((const float4*)(bi + n0));
        const float4 h0 = __ldg((const float4*)(bh + n0));
        const float4 i1 = __ldg((const float4*)(bi + n1));
        const float4 h1 = __ldg((const float4*)(bh + n1));
        bia0 = make_float4(i0.x + h0.x, i0.y + h0.y, i0.z + h0.z, i0.w + h0.w);
        bia1 = make_float4(i1.x + h1.x, i1.y + h1.y, i1.z + h1.z, i1.w + h1.w);
    }
    #pragma unroll
    for (int i = 0; i < 8; i++) {
        const int m = tm * 128 + (i < 4 ? ty * 4 + i : 64 + ty * 4 + (i - 4));
        const float2 c0 = up2(acc[i][0]), c1 = up2(acc[i][1]);
        const float2 c2 = up2(acc[i][2]), c3 = up2(acc[i][3]);
        *(float4*)(C + (size_t)m * HDIM + n0) =
            make_float4(c0.x + bia0.x, c0.y + bia0.y, c1.x + bia0.z, c1.y + bia0.w);
        *(float4*)(C + (size_t)m * HDIM + n1) =
            make_float4(c2.x + bia1.x, c2.y + bia1.y, c3.x + bia1.z, c3.y + bia1.w);
    }
}

// ============================================================================
// Recurrent scan, register-resident weights, TMA-bulk h staging.
// 128 CTAs x 256 thr (8 warps), 1 CTA/SM, CTA tile [16b x 32o].
// Warp w owns k-slice [128w, +128); lane l owns output o0+l.
// wreg = 64 u64 per lane (128 fp32), resident whole layer.
// h_{t-1} staged via 16 cp.async.bulk (4KB rows) + mbarrier — removes the
// per-thread LDGSTS LSU-issue floor (~8K cyc/step). h reads are warp-broadcast.
// ============================================================================
#define SM_MB  0                          // mbarrier (8B), float idx 0..1
#define SM_H   32                         // hS[16][1024] floats (128B aligned)
#define SM_R   (SM_H + 16 * 1024)         // red: u64[8][512]
#define SCAN_SMEM_BYTES ((SM_R) * 4 + 8 * 512 * 8)   // 98,432 B

__global__ void __launch_bounds__(256, 1) scan_kernel(
    const float* __restrict__ P, float* __restrict__ S,
    const float* __restrict__ Whh)
{
    extern __shared__ __align__(16) float sm[];
    float* hS = sm + SM_H;
    u64*   red = (u64*)(sm + SM_R);

    const int tid  = threadIdx.x;
    const int cta  = blockIdx.x;
    const int gbase = cta & ~31;        // barrier group base
    const int b0 = (cta >> 5) * 16;     // batch block
    const int o0 = (cta & 31) * 32;     // output block
    const int warp = tid >> 5;          // k-range owner: [warp*128, +128)
    const int lane = tid & 31;          // output owner: o0 + lane
    const int kb = warp * 128;

    const uint32_t mb   = smem_u32(sm + SM_MB);
    const uint32_t hS_a = smem_u32(hS);

    // ---- load this lane's weight slice into registers (once per layer) ----
    u64 wreg[64];
    {
        const float* wrow = Whh + (size_t)(o0 + lane) * HDIM + kb;
        #pragma unroll
        for (int c = 0; c < 32; c++) {
            const float4 w4 = __ldg((const float4*)(wrow + c * 4));
            wreg[2 * c]     = ((const u64*)&w4)[0];
            wreg[2 * c + 1] = ((const u64*)&w4)[1];
        }
    }

    // mbarrier init (fresh smem every launch)
    if (tid == 0) {
        mbar_init(mb, 1);
        fence_proxy_async_shared();
    }

    unsigned gen = g_flags[cta];        // persists across launches

    // Epilogue mapping: 2 adjacent outputs per thread
    const int pb = tid >> 4;
    const int po = (tid & 15) * 2;
    const size_t prow = ((size_t)(b0 + pb) * SEQT) * HDIM + o0 + po;

    // t = 0 (gsync provides the __syncthreads covering mbar_init)
    {
        const float2 p2 = *(const float2*)(P + prow);
        *(float2*)(S + prow) = make_float2(fmaxf(p2.x, 0.f), fmaxf(p2.y, 0.f));
    }
    gen++; gsync(gen, gbase);

    const float* Sb = S + (size_t)b0 * SEQT * HDIM;

    for (int t = 1; t < SEQT; t++) {
        const float2 p2 = __ldg((const float2*)(P + prow + (size_t)t * HDIM));

        // TMA bulk staging of h_{t-1}[b0..b0+16): 16 rows x 4KB.
        // Safe to overwrite hS: previous gsync synced all readers.
        if (tid == 0) {
            mbar_expect_tx(mb, 16 * 4096);
            const size_t tprev = (size_t)(t - 1) * HDIM;
            #pragma unroll
            for (int bb = 0; bb < 16; bb++)
                bulk_g2s(hS_a + bb * 4096,
                         Sb + (size_t)bb * SEQT * HDIM + tprev,
                         4096, mb);
        }
        mbar_wait(mb, (t - 1) & 1);

        // ---- compute: per lane, 16 batches x 1 output x 128 k ----
        u64 accF[16];
        #pragma unroll
        for (int b = 0; b < 16; b++) {
            const ulonglong2* hrow = (const ulonglong2*)&hS[b * 1024 + kb];
            u64 a0 = 0ull, a1 = 0ull;      // two interleaved chains
            #pragma unroll
            for (int c = 0; c < 32; c++) {
                const ulonglong2 hp = hrow[c];   // broadcast across warp
                fma2(a0, hp.x, wreg[2 * c]);
                fma2(a1, hp.y, wreg[2 * c + 1]);
            }
            accF[b] = add2(a0, a1);
        }

        // stash warp partials: red[warp][b][lane]
        #pragma unroll
        for (int b = 0; b < 16; b++)
            red[warp * 512 + b * 32 + lane] = accF[b];
        __syncthreads();

        // final reduce over 8 warps, fold (even,odd) k halves, relu, store
        {
            ulonglong2 v = *(const ulonglong2*)&red[pb * 32 + po];
            u64 s0 = v.x, s1 = v.y;
            #pragma unroll
            for (int w8 = 1; w8 < 8; w8++) {
                const ulonglong2 r = *(const ulonglong2*)&red[w8 * 512 + pb * 32 + po];
                s0 = add2(s0, r.x);
                s1 = add2(s1, r.y);
            }
            const float2 a0 = up2(s0), a1 = up2(s1);
            *(float2*)(S + prow + (size_t)t * HDIM) =
                make_float2(fmaxf(a0.x + a0.y + p2.x, 0.f),
                            fmaxf(a1.x + a1.y + p2.y, 0.f));
        }
        gen++; gsync(gen, gbase);
    }
}

// ============================================================================
// FC: out[64][128] = S[:, T-1, :] @ fc_w^T + fc_b
// ============================================================================
__global__ void __launch_bounds__(128) fc_kernel(
    const float* __restrict__ S, const float* __restrict__ fw,
    const float* __restrict__ fb, float* __restrict__ out)
{
    __shared__ __align__(16) float sx[HDIM];
    const int b = blockIdx.x, tid = threadIdx.x;
    const float* xrow = S + ((size_t)b * SEQT + (SEQT - 1)) * HDIM;
    for (int i = tid; i < HDIM / 4; i += 128)
        *(float4*)&sx[i * 4] = __ldcg((const float4*)(xrow + i * 4));
    __syncthreads();
    float acc = 0.f;
    const float* wrow = fw + (size_t)tid * HDIM;
    #pragma unroll 8
    for (int q = 0; q < HDIM / 4; q++) {
        const float4 w4 = __ldg((const float4*)(wrow + q * 4));
        const float4 x4 = *(const float4*)&sx[q * 4];
        acc += w4.x * x4.x + w4.y * x4.y + w4.z * x4.z + w4.w * x4.w;
    }
    out[(size_t)b * DOUT + tid] = acc + __ldg(fb + tid);
}

// ============================================================================
extern "C" void kernel_launch(void* const* d_in, const int* in_sizes, int n_in,
                              void* d_out, int out_size)
{
    const float* x    = (const float*)d_in[0];   // [64,512,256]
    const float* wih0 = (const float*)d_in[1];   // [1024,256]
    const float* wihr = (const float*)d_in[2];   // [2,1024,1024]
    const float* whh  = (const float*)d_in[3];   // [3,1024,1024]
    const float* bih  = (const float*)d_in[4];   // [3,1024]
    const float* bhh  = (const float*)d_in[5];   // [3,1024]
    const float* fcw  = (const float*)d_in[6];   // [128,1024]
    const float* fcb  = (const float*)d_in[7];   // [128]
    float* out = (float*)d_out;                  // [64,128]

    cudaFuncSetAttribute(scan_kernel, cudaFuncAttributeMaxDynamicSharedMemorySize,
                         SCAN_SMEM_BYTES);

    void *pP = nullptr, *pS = nullptr;
    cudaGetSymbolAddress(&pP, g_P);
    cudaGetSymbolAddress(&pS, g_S);
    float* P  = (float*)pP;
    float* Sq = (float*)pS;

    proj_kernel<<<2048, 256>>>(x, wih0, bih, bhh, P, DIN);
    scan_kernel<<<GRID, 256, SCAN_SMEM_BYTES>>>(P, Sq, whh);
    proj_kernel<<<2048, 256>>>(Sq, wihr, bih + HDIM, bhh + HDIM, P, HDIM);
    scan_kernel<<<GRID, 256, SCAN_SMEM_BYTES>>>(P, Sq, whh + (size_t)HDIM * HDIM);
    proj_kernel<<<2048, 256>>>(Sq, wihr + (size_t)HDIM * HDIM, bih + 2 * HDIM, bhh + 2 * HDIM, P, HDIM);
    scan_kernel<<<GRID, 256, SCAN_SMEM_BYTES>>>(P, Sq, whh + 2 * (size_t)HDIM * HDIM);
    fc_kernel<<<BATCH, 128>>>(Sq, fcw, fcb, out);
}